// round 14
// baseline (speedup 1.0000x reference)
#include <cuda_runtime.h>
#include <cuda_fp16.h>
#include <math.h>

#define NN 20000
#define EE 320000
#define DIM 128
#define GDIM 512          // HEADS * DIM
#define NHEADS 4
#define NB 16
#define NACT 10
#define NEG_SLOPE 0.2f

// ---------------- scratch (static __device__, no allocs) ----------------
static __device__ int    d_deg[NN];
static __device__ int    d_rowptr[NN + 1];
static __device__ int    d_wptr[NN];
static __device__ int    d_csrsrc[EE];
static __device__ float  d_nm[NN * DIM];          // neighbor mean
static __device__ float  d_h[NN * DIM];           // SAGE output
static __device__ float  d_g[(size_t)NN * GDIM];  // GAT transformed feats (fp32, for k_attn)
static __device__ __half d_g16[(size_t)NN * GDIM]; // head-interleaved fp16 copy for gathers
static __device__ float  d_as[NN * NHEADS];
static __device__ float  d_ad[NN * NHEADS];
static __device__ float  d_h2[NN * DIM];          // GAT output
static __device__ float  d_pool[NB * DIM];
static __device__ float  d_pcnt[NB];

// ---------------- kernels ----------------

__global__ void k_zero() {
    int i = blockIdx.x * blockDim.x + threadIdx.x;
    if (i < NN) { d_deg[i] = 0; d_wptr[i] = 0; }
    if (i < NB * DIM) d_pool[i] = 0.f;
    if (i < NB) d_pcnt[i] = 0.f;
}

__global__ void k_count(const int* __restrict__ ei) {
    int i = blockIdx.x * blockDim.x + threadIdx.x;
    if (i < EE) atomicAdd(&d_deg[ei[EE + i]], 1);
}

// single-block scan, warp-shuffle based
__global__ void k_scan() {
    __shared__ int wsum[32];
    __shared__ int carry_s;
    int tid = threadIdx.x, lane = tid & 31, wid = tid >> 5;
    if (tid == 0) { carry_s = 0; d_rowptr[0] = 0; }
    __syncthreads();
    for (int base = 0; base < NN; base += 1024) {
        int i = base + tid;
        int v = (i < NN) ? d_deg[i] : 0;
        int s = v;
#pragma unroll
        for (int o = 1; o < 32; o <<= 1) {
            int t = __shfl_up_sync(0xffffffffu, s, o);
            if (lane >= o) s += t;
        }
        if (lane == 31) wsum[wid] = s;
        __syncthreads();
        if (wid == 0) {
            int w = wsum[lane];
#pragma unroll
            for (int o = 1; o < 32; o <<= 1) {
                int t = __shfl_up_sync(0xffffffffu, w, o);
                if (lane >= o) w += t;
            }
            wsum[lane] = w;
        }
        __syncthreads();
        int off = (wid > 0) ? wsum[wid - 1] : 0;
        int inc = s + off + carry_s;
        if (i < NN) d_rowptr[i + 1] = inc;
        __syncthreads();
        if (tid == 1023) carry_s = inc;
        __syncthreads();
    }
}

__global__ void k_scatter(const int* __restrict__ ei) {
    int i = blockIdx.x * blockDim.x + threadIdx.x;
    if (i < EE) {
        int s = ei[i];
        int t = ei[EE + i];
        int pos = d_rowptr[t] + atomicAdd(&d_wptr[t], 1);
        d_csrsrc[pos] = s;
    }
}

// neighbor mean: one block per node, 128 threads (one per channel)
__global__ void k_sage_agg(const float* __restrict__ x) {
    int n = blockIdx.x;
    int tid = threadIdx.x;
    int beg = d_rowptr[n], end = d_rowptr[n + 1];
    float acc = 0.f;
    for (int j = beg; j < end; j++) {
        int s = d_csrsrc[j];
        acc += x[(size_t)s * DIM + tid];
    }
    float deg = (float)(end - beg);
    d_nm[n * DIM + tid] = acc / fmaxf(deg, 1.f);
}

// h = elu(nm@W_l + x@W_r + b) ; 8 nodes per block, 128 threads
__global__ void __launch_bounds__(128) k_sage_lin(
        const float* __restrict__ x,
        const float* __restrict__ Wl,
        const float* __restrict__ Wr,
        const float* __restrict__ bs) {
    __shared__ float4 sm4[8][32], sx4[8][32];
    int tid = threadIdx.x;
    int n0 = blockIdx.x * 8;
#pragma unroll
    for (int i = 0; i < 2; i++) {
        int idx = i * 128 + tid;
        int row = idx >> 5, col = idx & 31;
        sm4[row][col] = ((const float4*)d_nm)[(n0 + row) * 32 + col];
        sx4[row][col] = ((const float4*)x)[(size_t)(n0 + row) * 32 + col];
    }
    __syncthreads();
    float b = bs[tid];
    float acc[8];
#pragma unroll
    for (int r = 0; r < 8; r++) acc[r] = b;
    for (int kk = 0; kk < 32; kk++) {
        float wl0 = Wl[(4 * kk + 0) * DIM + tid];
        float wl1 = Wl[(4 * kk + 1) * DIM + tid];
        float wl2 = Wl[(4 * kk + 2) * DIM + tid];
        float wl3 = Wl[(4 * kk + 3) * DIM + tid];
        float wr0 = Wr[(4 * kk + 0) * DIM + tid];
        float wr1 = Wr[(4 * kk + 1) * DIM + tid];
        float wr2 = Wr[(4 * kk + 2) * DIM + tid];
        float wr3 = Wr[(4 * kk + 3) * DIM + tid];
#pragma unroll
        for (int r = 0; r < 8; r++) {
            float4 m = sm4[r][kk];
            float4 xx = sx4[r][kk];
            acc[r] += m.x * wl0 + m.y * wl1 + m.z * wl2 + m.w * wl3
                    + xx.x * wr0 + xx.y * wr1 + xx.z * wr2 + xx.w * wr3;
        }
    }
#pragma unroll
    for (int r = 0; r < 8; r++)
        d_h[(n0 + r) * DIM + tid] = acc[r] > 0.f ? acc[r] : __expf(acc[r]) - 1.f;
}

// g = h@W_gat ; 16 nodes/block, 512 threads.
// Epilogue writes fp32 d_g (for k_attn) and head-interleaved fp16 d_g16
// (layout [node][channel][head]) for the gat_agg gathers.
__global__ void __launch_bounds__(512) k_gat_lin(const float* __restrict__ Wg) {
    __shared__ float4 sh4[16][32];
    int tid = threadIdx.x;
    int n0 = blockIdx.x * 16;
    {
        int row = tid >> 5, col = tid & 31;
        sh4[row][col] = ((const float4*)d_h)[(n0 + row) * 32 + col];
    }
    __syncthreads();
    float acc[16];
#pragma unroll
    for (int r = 0; r < 16; r++) acc[r] = 0.f;
    for (int kk = 0; kk < 32; kk++) {
        float w0 = Wg[(4 * kk + 0) * GDIM + tid];
        float w1 = Wg[(4 * kk + 1) * GDIM + tid];
        float w2 = Wg[(4 * kk + 2) * GDIM + tid];
        float w3 = Wg[(4 * kk + 3) * GDIM + tid];
#pragma unroll
        for (int r = 0; r < 16; r++) {
            float4 m = sh4[r][kk];
            acc[r] += m.x * w0 + m.y * w1 + m.z * w2 + m.w * w3;
        }
    }
    int h = tid >> 7, c = tid & 127;
#pragma unroll
    for (int r = 0; r < 16; r++) {
        d_g[(size_t)(n0 + r) * GDIM + tid] = acc[r];
        d_g16[(size_t)(n0 + r) * GDIM + c * NHEADS + h] = __float2half(acc[r]);
    }
}

// a_s, a_d: one warp per (node, head)
__global__ void k_attn(const float* __restrict__ att_s,
                       const float* __restrict__ att_d) {
    int gw = (blockIdx.x * blockDim.x + threadIdx.x) >> 5;
    if (gw >= NN * NHEADS) return;
    int l = threadIdx.x & 31;
    int n = gw >> 2, h = gw & 3;
    float4 gv = ((const float4*)d_g)[(size_t)n * 128 + h * 32 + l];
    float4 sv = ((const float4*)att_s)[h * 32 + l];
    float4 dv = ((const float4*)att_d)[h * 32 + l];
    float as = gv.x * sv.x + gv.y * sv.y + gv.z * sv.z + gv.w * sv.w;
    float ad = gv.x * dv.x + gv.y * dv.y + gv.z * dv.z + gv.w * dv.w;
#pragma unroll
    for (int o = 16; o; o >>= 1) {
        as += __shfl_xor_sync(0xffffffffu, as, o);
        ad += __shfl_xor_sync(0xffffffffu, ad, o);
    }
    if (l == 0) { d_as[n * 4 + h] = as; d_ad[n * 4 + h] = ad; }
}

// GAT softmax-aggregate per dst node + fused mean-pool accumulate.
// No max subtraction (shift-invariant; logits far from fp32 overflow).
// Messages gathered from fp16 head-interleaved d_g16: one 8B load per edge
// per thread (4 heads at this thread's channel).
__global__ void k_gat_agg(const int* __restrict__ batch,
                          const float* __restrict__ b_gat) {
    int n = blockIdx.x;
    int tid = threadIdx.x;
    int beg = d_rowptr[n], end = d_rowptr[n + 1];

    float ad0 = d_ad[n * NHEADS + 0], ad1 = d_ad[n * NHEADS + 1];
    float ad2 = d_ad[n * NHEADS + 2], ad3 = d_ad[n * NHEADS + 3];
    float acc0 = 0.f, acc1 = 0.f, acc2 = 0.f, acc3 = 0.f;
    float den0 = 0.f, den1 = 0.f, den2 = 0.f, den3 = 0.f;
    const float4* as4 = (const float4*)d_as;
    const __half2* g2 = (const __half2*)d_g16;
    for (int j = beg; j < end; j++) {
        int s = d_csrsrc[j];
        float4 av = as4[s];
        float v0 = av.x + ad0; v0 = v0 > 0.f ? v0 : NEG_SLOPE * v0;
        float v1 = av.y + ad1; v1 = v1 > 0.f ? v1 : NEG_SLOPE * v1;
        float v2 = av.z + ad2; v2 = v2 > 0.f ? v2 : NEG_SLOPE * v2;
        float v3 = av.w + ad3; v3 = v3 > 0.f ? v3 : NEG_SLOPE * v3;
        float e0 = __expf(v0);
        float e1 = __expf(v1);
        float e2 = __expf(v2);
        float e3 = __expf(v3);
        den0 += e0; den1 += e1; den2 += e2; den3 += e3;
        // 8-byte load: heads 0..3 at channel tid
        size_t base = (size_t)s * (GDIM / 2) + tid * 2;
        __half2 p01 = g2[base];
        __half2 p23 = g2[base + 1];
        float2 f01 = __half22float2(p01);
        float2 f23 = __half22float2(p23);
        acc0 += e0 * f01.x;
        acc1 += e1 * f01.y;
        acc2 += e2 * f23.x;
        acc3 += e3 * f23.y;
    }
    float o = acc0 / (den0 + 1e-16f) + acc1 / (den1 + 1e-16f)
            + acc2 / (den2 + 1e-16f) + acc3 / (den3 + 1e-16f);
    o = o * 0.25f + b_gat[tid];
    float hv = o > 0.f ? o : __expf(o) - 1.f;
    d_h2[n * DIM + tid] = hv;
    int b = batch[n];
    atomicAdd(&d_pool[b * DIM + tid], hv);
    if (tid == 0) atomicAdd(&d_pcnt[b], 1.f);
}

// wire / term heads: one warp per node
__global__ void k_heads(const float* __restrict__ Ww, const float* __restrict__ bw,
                        const float* __restrict__ Wt, const float* __restrict__ bt,
                        float* __restrict__ out) {
    int w = (blockIdx.x * blockDim.x + threadIdx.x) >> 5;
    if (w >= NN) return;
    int lane = threadIdx.x & 31;
    const float* Wv;
    float bias;
    if (w < NN - 10) { Wv = Ww; bias = bw[0]; }
    else             { Wv = Wt; bias = bt[0]; }
    float a = 0.f;
#pragma unroll
    for (int c = lane; c < DIM; c += 32) a += d_h2[w * DIM + c] * Wv[c];
#pragma unroll
    for (int off = 16; off > 0; off >>= 1)
        a += __shfl_xor_sync(0xffffffffu, a, off);
    if (lane == 0) out[w] = 1.f / (1.f + __expf(-(a + bias)));
}

__global__ void k_logits(const float* __restrict__ Wa, const float* __restrict__ ba,
                         float* __restrict__ out) {
    __shared__ float sp[DIM];
    int b = blockIdx.x;
    int tid = threadIdx.x;
    float cnt = fmaxf(d_pcnt[b], 1.f);
    sp[tid] = d_pool[b * DIM + tid] / cnt;
    __syncthreads();
    if (tid < NACT) {
        float a = ba[tid];
#pragma unroll 8
        for (int c = 0; c < DIM; c++) a += sp[c] * Wa[c * NACT + tid];
        out[NN + b * NACT + tid] = a;
    }
}

// ---------------- launch ----------------
extern "C" void kernel_launch(void* const* d_in, const int* in_sizes, int n_in,
                              void* d_out, int out_size) {
    const float* x     = (const float*)d_in[0];
    const int*   ei    = (const int*)d_in[1];
    const int*   batch = (const int*)d_in[2];
    const float* Wl   = (const float*)d_in[3];
    const float* Wr   = (const float*)d_in[4];
    const float* bs   = (const float*)d_in[5];
    const float* Wg   = (const float*)d_in[6];
    const float* ats  = (const float*)d_in[7];
    const float* atd  = (const float*)d_in[8];
    const float* bg   = (const float*)d_in[9];
    const float* Ww   = (const float*)d_in[10];
    const float* bw   = (const float*)d_in[11];
    const float* Wt   = (const float*)d_in[12];
    const float* bt   = (const float*)d_in[13];
    const float* Wa   = (const float*)d_in[14];
    const float* ba   = (const float*)d_in[15];
    float* out = (float*)d_out;

    k_zero<<<(NN + 255) / 256, 256>>>();
    k_count<<<EE / 256, 256>>>(ei);
    k_scan<<<1, 1024>>>();
    k_scatter<<<EE / 256, 256>>>(ei);
    k_sage_agg<<<NN, DIM>>>(x);
    k_sage_lin<<<NN / 8, DIM>>>(x, Wl, Wr, bs);
    k_gat_lin<<<NN / 16, GDIM>>>(Wg);
    k_attn<<<(NN * NHEADS * 32) / 256, 256>>>(ats, atd);
    k_gat_agg<<<NN, DIM>>>(batch, bg);
    k_heads<<<(NN * 32 + 127) / 128, 128>>>(Ww, bw, Wt, bt, out);
    k_logits<<<NB, DIM>>>(Wa, ba, out);
}

// round 15
// speedup vs baseline: 1.0445x; 1.0445x over previous
#include <cuda_runtime.h>
#include <math.h>

#define NN 20000
#define EE 320000
#define DIM 128
#define GDIM 512          // HEADS * DIM
#define NHEADS 4
#define NB 16
#define NACT 10
#define NEG_SLOPE 0.2f

// ---------------- scratch (static __device__, no allocs) ----------------
static __device__ int   d_deg[NN];
static __device__ int   d_rowptr[NN + 1];
static __device__ int   d_wptr[NN];
static __device__ int   d_csrsrc[EE];
static __device__ float d_nm[NN * DIM];          // neighbor mean
static __device__ float d_h[NN * DIM];           // SAGE output
static __device__ float d_g[(size_t)NN * GDIM];  // GAT transformed feats
static __device__ float d_as[NN * NHEADS];
static __device__ float d_ad[NN * NHEADS];
static __device__ float d_h2[NN * DIM];          // GAT output
static __device__ float d_pool[NB * DIM];
static __device__ float d_pcnt[NB];

// ---------------- kernels ----------------

__global__ void k_zero() {
    int i = blockIdx.x * blockDim.x + threadIdx.x;
    if (i < NN) { d_deg[i] = 0; d_wptr[i] = 0; }
    if (i < NB * DIM) d_pool[i] = 0.f;
    if (i < NB) d_pcnt[i] = 0.f;
}

__global__ void k_count(const int* __restrict__ ei) {
    int i = blockIdx.x * blockDim.x + threadIdx.x;
    if (i < EE) atomicAdd(&d_deg[ei[EE + i]], 1);
}

// single-block scan, warp-shuffle based
__global__ void k_scan() {
    __shared__ int wsum[32];
    __shared__ int carry_s;
    int tid = threadIdx.x, lane = tid & 31, wid = tid >> 5;
    if (tid == 0) { carry_s = 0; d_rowptr[0] = 0; }
    __syncthreads();
    for (int base = 0; base < NN; base += 1024) {
        int i = base + tid;
        int v = (i < NN) ? d_deg[i] : 0;
        int s = v;
#pragma unroll
        for (int o = 1; o < 32; o <<= 1) {
            int t = __shfl_up_sync(0xffffffffu, s, o);
            if (lane >= o) s += t;
        }
        if (lane == 31) wsum[wid] = s;
        __syncthreads();
        if (wid == 0) {
            int w = wsum[lane];
#pragma unroll
            for (int o = 1; o < 32; o <<= 1) {
                int t = __shfl_up_sync(0xffffffffu, w, o);
                if (lane >= o) w += t;
            }
            wsum[lane] = w;
        }
        __syncthreads();
        int off = (wid > 0) ? wsum[wid - 1] : 0;
        int inc = s + off + carry_s;
        if (i < NN) d_rowptr[i + 1] = inc;
        __syncthreads();
        if (tid == 1023) carry_s = inc;
        __syncthreads();
    }
}

__global__ void k_scatter(const int* __restrict__ ei) {
    int i = blockIdx.x * blockDim.x + threadIdx.x;
    if (i < EE) {
        int s = ei[i];
        int t = ei[EE + i];
        int pos = d_rowptr[t] + atomicAdd(&d_wptr[t], 1);
        d_csrsrc[pos] = s;
    }
}

// neighbor mean: one block per node, 128 threads (one per channel)
__global__ void k_sage_agg(const float* __restrict__ x) {
    int n = blockIdx.x;
    int tid = threadIdx.x;
    int beg = d_rowptr[n], end = d_rowptr[n + 1];
    float acc = 0.f;
    for (int j = beg; j < end; j++) {
        int s = d_csrsrc[j];
        acc += x[(size_t)s * DIM + tid];
    }
    float deg = (float)(end - beg);
    d_nm[n * DIM + tid] = acc / fmaxf(deg, 1.f);
}

// h = elu(nm@W_l + x@W_r + b) ; 8 nodes per block, 128 threads
__global__ void __launch_bounds__(128) k_sage_lin(
        const float* __restrict__ x,
        const float* __restrict__ Wl,
        const float* __restrict__ Wr,
        const float* __restrict__ bs) {
    __shared__ float4 sm4[8][32], sx4[8][32];
    int tid = threadIdx.x;
    int n0 = blockIdx.x * 8;
#pragma unroll
    for (int i = 0; i < 2; i++) {
        int idx = i * 128 + tid;
        int row = idx >> 5, col = idx & 31;
        sm4[row][col] = ((const float4*)d_nm)[(n0 + row) * 32 + col];
        sx4[row][col] = ((const float4*)x)[(size_t)(n0 + row) * 32 + col];
    }
    __syncthreads();
    float b = bs[tid];
    float acc[8];
#pragma unroll
    for (int r = 0; r < 8; r++) acc[r] = b;
    for (int kk = 0; kk < 32; kk++) {
        float wl0 = Wl[(4 * kk + 0) * DIM + tid];
        float wl1 = Wl[(4 * kk + 1) * DIM + tid];
        float wl2 = Wl[(4 * kk + 2) * DIM + tid];
        float wl3 = Wl[(4 * kk + 3) * DIM + tid];
        float wr0 = Wr[(4 * kk + 0) * DIM + tid];
        float wr1 = Wr[(4 * kk + 1) * DIM + tid];
        float wr2 = Wr[(4 * kk + 2) * DIM + tid];
        float wr3 = Wr[(4 * kk + 3) * DIM + tid];
#pragma unroll
        for (int r = 0; r < 8; r++) {
            float4 m = sm4[r][kk];
            float4 xx = sx4[r][kk];
            acc[r] += m.x * wl0 + m.y * wl1 + m.z * wl2 + m.w * wl3
                    + xx.x * wr0 + xx.y * wr1 + xx.z * wr2 + xx.w * wr3;
        }
    }
#pragma unroll
    for (int r = 0; r < 8; r++)
        d_h[(n0 + r) * DIM + tid] = acc[r] > 0.f ? acc[r] : __expf(acc[r]) - 1.f;
}

// g = h@W_gat ; 16 nodes/block, 512 threads
__global__ void __launch_bounds__(512) k_gat_lin(const float* __restrict__ Wg) {
    __shared__ float4 sh4[16][32];
    int tid = threadIdx.x;
    int n0 = blockIdx.x * 16;
    {
        int row = tid >> 5, col = tid & 31;
        sh4[row][col] = ((const float4*)d_h)[(n0 + row) * 32 + col];
    }
    __syncthreads();
    float acc[16];
#pragma unroll
    for (int r = 0; r < 16; r++) acc[r] = 0.f;
    for (int kk = 0; kk < 32; kk++) {
        float w0 = Wg[(4 * kk + 0) * GDIM + tid];
        float w1 = Wg[(4 * kk + 1) * GDIM + tid];
        float w2 = Wg[(4 * kk + 2) * GDIM + tid];
        float w3 = Wg[(4 * kk + 3) * GDIM + tid];
#pragma unroll
        for (int r = 0; r < 16; r++) {
            float4 m = sh4[r][kk];
            acc[r] += m.x * w0 + m.y * w1 + m.z * w2 + m.w * w3;
        }
    }
#pragma unroll
    for (int r = 0; r < 16; r++)
        d_g[(size_t)(n0 + r) * GDIM + tid] = acc[r];
}

// a_s, a_d: one warp per (node, head)
__global__ void k_attn(const float* __restrict__ att_s,
                       const float* __restrict__ att_d) {
    int gw = (blockIdx.x * blockDim.x + threadIdx.x) >> 5;
    if (gw >= NN * NHEADS) return;
    int l = threadIdx.x & 31;
    int n = gw >> 2, h = gw & 3;
    float4 gv = ((const float4*)d_g)[(size_t)n * 128 + h * 32 + l];
    float4 sv = ((const float4*)att_s)[h * 32 + l];
    float4 dv = ((const float4*)att_d)[h * 32 + l];
    float as = gv.x * sv.x + gv.y * sv.y + gv.z * sv.z + gv.w * sv.w;
    float ad = gv.x * dv.x + gv.y * dv.y + gv.z * dv.z + gv.w * dv.w;
#pragma unroll
    for (int o = 16; o; o >>= 1) {
        as += __shfl_xor_sync(0xffffffffu, as, o);
        ad += __shfl_xor_sync(0xffffffffu, ad, o);
    }
    if (l == 0) { d_as[n * 4 + h] = as; d_ad[n * 4 + h] = ad; }
}

// GAT softmax-aggregate per dst node + fused mean-pool accumulate.
// No max subtraction (shift-invariant; logits far from fp32 overflow).
// exp() computed ONCE per (edge, head) by 32 threads into smem, then the
// accumulate loop reads e by smem broadcast — removes the 128x redundant
// MUFU work that bound this kernel.
__global__ void k_gat_agg(const int* __restrict__ batch,
                          const float* __restrict__ b_gat) {
    __shared__ float4 se[32];
    __shared__ int    ss[32];
    int n = blockIdx.x;
    int tid = threadIdx.x;
    int beg = d_rowptr[n], end = d_rowptr[n + 1];

    float ad0 = d_ad[n * NHEADS + 0], ad1 = d_ad[n * NHEADS + 1];
    float ad2 = d_ad[n * NHEADS + 2], ad3 = d_ad[n * NHEADS + 3];
    float acc0 = 0.f, acc1 = 0.f, acc2 = 0.f, acc3 = 0.f;
    float den0 = 0.f, den1 = 0.f, den2 = 0.f, den3 = 0.f;
    const float4* as4 = (const float4*)d_as;

    for (int chunk = beg; chunk < end; chunk += 32) {
        int m = min(32, end - chunk);
        if (tid < m) {
            int s = d_csrsrc[chunk + tid];
            ss[tid] = s;
            float4 av = as4[s];
            float v0 = av.x + ad0; v0 = v0 > 0.f ? v0 : NEG_SLOPE * v0;
            float v1 = av.y + ad1; v1 = v1 > 0.f ? v1 : NEG_SLOPE * v1;
            float v2 = av.z + ad2; v2 = v2 > 0.f ? v2 : NEG_SLOPE * v2;
            float v3 = av.w + ad3; v3 = v3 > 0.f ? v3 : NEG_SLOPE * v3;
            se[tid] = make_float4(__expf(v0), __expf(v1), __expf(v2), __expf(v3));
        }
        __syncthreads();
        for (int t = 0; t < m; t++) {
            int s = ss[t];
            float4 e = se[t];
            den0 += e.x; den1 += e.y; den2 += e.z; den3 += e.w;
            const float* gs = d_g + (size_t)s * GDIM;
            acc0 += e.x * gs[tid];
            acc1 += e.y * gs[DIM + tid];
            acc2 += e.z * gs[2 * DIM + tid];
            acc3 += e.w * gs[3 * DIM + tid];
        }
        __syncthreads();
    }
    float o = acc0 / (den0 + 1e-16f) + acc1 / (den1 + 1e-16f)
            + acc2 / (den2 + 1e-16f) + acc3 / (den3 + 1e-16f);
    o = o * 0.25f + b_gat[tid];
    float hv = o > 0.f ? o : __expf(o) - 1.f;
    d_h2[n * DIM + tid] = hv;
    int b = batch[n];
    atomicAdd(&d_pool[b * DIM + tid], hv);
    if (tid == 0) atomicAdd(&d_pcnt[b], 1.f);
}

// wire / term heads: one warp per node
__global__ void k_heads(const float* __restrict__ Ww, const float* __restrict__ bw,
                        const float* __restrict__ Wt, const float* __restrict__ bt,
                        float* __restrict__ out) {
    int w = (blockIdx.x * blockDim.x + threadIdx.x) >> 5;
    if (w >= NN) return;
    int lane = threadIdx.x & 31;
    const float* Wv;
    float bias;
    if (w < NN - 10) { Wv = Ww; bias = bw[0]; }
    else             { Wv = Wt; bias = bt[0]; }
    float a = 0.f;
#pragma unroll
    for (int c = lane; c < DIM; c += 32) a += d_h2[w * DIM + c] * Wv[c];
#pragma unroll
    for (int off = 16; off > 0; off >>= 1)
        a += __shfl_xor_sync(0xffffffffu, a, off);
    if (lane == 0) out[w] = 1.f / (1.f + __expf(-(a + bias)));
}

__global__ void k_logits(const float* __restrict__ Wa, const float* __restrict__ ba,
                         float* __restrict__ out) {
    __shared__ float sp[DIM];
    int b = blockIdx.x;
    int tid = threadIdx.x;
    float cnt = fmaxf(d_pcnt[b], 1.f);
    sp[tid] = d_pool[b * DIM + tid] / cnt;
    __syncthreads();
    if (tid < NACT) {
        float a = ba[tid];
#pragma unroll 8
        for (int c = 0; c < DIM; c++) a += sp[c] * Wa[c * NACT + tid];
        out[NN + b * NACT + tid] = a;
    }
}

// ---------------- launch ----------------
extern "C" void kernel_launch(void* const* d_in, const int* in_sizes, int n_in,
                              void* d_out, int out_size) {
    const float* x     = (const float*)d_in[0];
    const int*   ei    = (const int*)d_in[1];
    const int*   batch = (const int*)d_in[2];
    const float* Wl   = (const float*)d_in[3];
    const float* Wr   = (const float*)d_in[4];
    const float* bs   = (const float*)d_in[5];
    const float* Wg   = (const float*)d_in[6];
    const float* ats  = (const float*)d_in[7];
    const float* atd  = (const float*)d_in[8];
    const float* bg   = (const float*)d_in[9];
    const float* Ww   = (const float*)d_in[10];
    const float* bw   = (const float*)d_in[11];
    const float* Wt   = (const float*)d_in[12];
    const float* bt   = (const float*)d_in[13];
    const float* Wa   = (const float*)d_in[14];
    const float* ba   = (const float*)d_in[15];
    float* out = (float*)d_out;

    k_zero<<<(NN + 255) / 256, 256>>>();
    k_count<<<EE / 256, 256>>>(ei);
    k_scan<<<1, 1024>>>();
    k_scatter<<<EE / 256, 256>>>(ei);
    k_sage_agg<<<NN, DIM>>>(x);
    k_sage_lin<<<NN / 8, DIM>>>(x, Wl, Wr, bs);
    k_gat_lin<<<NN / 16, GDIM>>>(Wg);
    k_attn<<<(NN * NHEADS * 32) / 256, 256>>>(ats, atd);
    k_gat_agg<<<NN, DIM>>>(batch, bg);
    k_heads<<<(NN * 32 + 127) / 128, 128>>>(Ww, bw, Wt, bt, out);
    k_logits<<<NB, DIM>>>(Wa, ba, out);
}

// round 17
// speedup vs baseline: 1.0648x; 1.0195x over previous
#include <cuda_runtime.h>
#include <math.h>

#define NN 20000
#define EE 320000
#define DIM 128
#define GDIM 512          // HEADS * DIM
#define NHEADS 4
#define NB 16
#define NACT 10
#define NEG_SLOPE 0.2f

// ---------------- scratch (static __device__, no allocs) ----------------
// NOTE: relies on zero-initialization of __device__ globals for the FIRST
// launch; every execution leaves d_deg (countdown scatter) and d_pool/d_pcnt
// (zeroed after read in k_heads_logits) at zero for the next replay.
static __device__ int   d_deg[NN];
static __device__ int   d_rowptr[NN + 1];
static __device__ int   d_csrsrc[EE];
static __device__ float d_nm[NN * DIM];          // neighbor mean
static __device__ float d_h[NN * DIM];           // SAGE output
static __device__ float d_g[(size_t)NN * GDIM];  // GAT transformed feats
static __device__ float d_as[NN * NHEADS];
static __device__ float d_ad[NN * NHEADS];
static __device__ float d_h2[NN * DIM];          // GAT output
static __device__ float d_pool[NB * DIM];
static __device__ float d_pcnt[NB];

// ---------------- kernels ----------------

__global__ void k_count(const int* __restrict__ ei) {
    int i = blockIdx.x * blockDim.x + threadIdx.x;
    if (i < EE) atomicAdd(&d_deg[ei[EE + i]], 1);
}

// single-block scan, warp-shuffle based
__global__ void k_scan() {
    __shared__ int wsum[32];
    __shared__ int carry_s;
    int tid = threadIdx.x, lane = tid & 31, wid = tid >> 5;
    if (tid == 0) { carry_s = 0; d_rowptr[0] = 0; }
    __syncthreads();
    for (int base = 0; base < NN; base += 1024) {
        int i = base + tid;
        int v = (i < NN) ? d_deg[i] : 0;
        int s = v;
#pragma unroll
        for (int o = 1; o < 32; o <<= 1) {
            int t = __shfl_up_sync(0xffffffffu, s, o);
            if (lane >= o) s += t;
        }
        if (lane == 31) wsum[wid] = s;
        __syncthreads();
        if (wid == 0) {
            int w = wsum[lane];
#pragma unroll
            for (int o = 1; o < 32; o <<= 1) {
                int t = __shfl_up_sync(0xffffffffu, w, o);
                if (lane >= o) w += t;
            }
            wsum[lane] = w;
        }
        __syncthreads();
        int off = (wid > 0) ? wsum[wid - 1] : 0;
        int inc = s + off + carry_s;
        if (i < NN) d_rowptr[i + 1] = inc;
        __syncthreads();
        if (tid == 1023) carry_s = inc;
        __syncthreads();
    }
}

// scatter by COUNTING DOWN d_deg: pos = rowptr[t] + (old-1). Leaves d_deg == 0
// after completion (self-zeroing for the next graph replay); d_wptr eliminated.
__global__ void k_scatter(const int* __restrict__ ei) {
    int i = blockIdx.x * blockDim.x + threadIdx.x;
    if (i < EE) {
        int s = ei[i];
        int t = ei[EE + i];
        int old = atomicSub(&d_deg[t], 1);
        d_csrsrc[d_rowptr[t] + old - 1] = s;
    }
}

// neighbor mean: one block per node, 128 threads (one per channel)
__global__ void k_sage_agg(const float* __restrict__ x) {
    int n = blockIdx.x;
    int tid = threadIdx.x;
    int beg = d_rowptr[n], end = d_rowptr[n + 1];
    float acc = 0.f;
    for (int j = beg; j < end; j++) {
        int s = d_csrsrc[j];
        acc += x[(size_t)s * DIM + tid];
    }
    float deg = (float)(end - beg);
    d_nm[n * DIM + tid] = acc / fmaxf(deg, 1.f);
}

// h = elu(nm@W_l + x@W_r + b) ; 8 nodes per block, 128 threads
__global__ void __launch_bounds__(128) k_sage_lin(
        const float* __restrict__ x,
        const float* __restrict__ Wl,
        const float* __restrict__ Wr,
        const float* __restrict__ bs) {
    __shared__ float4 sm4[8][32], sx4[8][32];
    int tid = threadIdx.x;
    int n0 = blockIdx.x * 8;
#pragma unroll
    for (int i = 0; i < 2; i++) {
        int idx = i * 128 + tid;
        int row = idx >> 5, col = idx & 31;
        sm4[row][col] = ((const float4*)d_nm)[(n0 + row) * 32 + col];
        sx4[row][col] = ((const float4*)x)[(size_t)(n0 + row) * 32 + col];
    }
    __syncthreads();
    float b = bs[tid];
    float acc[8];
#pragma unroll
    for (int r = 0; r < 8; r++) acc[r] = b;
    for (int kk = 0; kk < 32; kk++) {
        float wl0 = Wl[(4 * kk + 0) * DIM + tid];
        float wl1 = Wl[(4 * kk + 1) * DIM + tid];
        float wl2 = Wl[(4 * kk + 2) * DIM + tid];
        float wl3 = Wl[(4 * kk + 3) * DIM + tid];
        float wr0 = Wr[(4 * kk + 0) * DIM + tid];
        float wr1 = Wr[(4 * kk + 1) * DIM + tid];
        float wr2 = Wr[(4 * kk + 2) * DIM + tid];
        float wr3 = Wr[(4 * kk + 3) * DIM + tid];
#pragma unroll
        for (int r = 0; r < 8; r++) {
            float4 m = sm4[r][kk];
            float4 xx = sx4[r][kk];
            acc[r] += m.x * wl0 + m.y * wl1 + m.z * wl2 + m.w * wl3
                    + xx.x * wr0 + xx.y * wr1 + xx.z * wr2 + xx.w * wr3;
        }
    }
#pragma unroll
    for (int r = 0; r < 8; r++)
        d_h[(n0 + r) * DIM + tid] = acc[r] > 0.f ? acc[r] : __expf(acc[r]) - 1.f;
}

// g = h@W_gat ; 16 nodes/block, 512 threads
__global__ void __launch_bounds__(512) k_gat_lin(const float* __restrict__ Wg) {
    __shared__ float4 sh4[16][32];
    int tid = threadIdx.x;
    int n0 = blockIdx.x * 16;
    {
        int row = tid >> 5, col = tid & 31;
        sh4[row][col] = ((const float4*)d_h)[(n0 + row) * 32 + col];
    }
    __syncthreads();
    float acc[16];
#pragma unroll
    for (int r = 0; r < 16; r++) acc[r] = 0.f;
    for (int kk = 0; kk < 32; kk++) {
        float w0 = Wg[(4 * kk + 0) * GDIM + tid];
        float w1 = Wg[(4 * kk + 1) * GDIM + tid];
        float w2 = Wg[(4 * kk + 2) * GDIM + tid];
        float w3 = Wg[(4 * kk + 3) * GDIM + tid];
#pragma unroll
        for (int r = 0; r < 16; r++) {
            float4 m = sh4[r][kk];
            acc[r] += m.x * w0 + m.y * w1 + m.z * w2 + m.w * w3;
        }
    }
#pragma unroll
    for (int r = 0; r < 16; r++)
        d_g[(size_t)(n0 + r) * GDIM + tid] = acc[r];
}

// a_s, a_d: one warp per (node, head)
__global__ void k_attn(const float* __restrict__ att_s,
                       const float* __restrict__ att_d) {
    int gw = (blockIdx.x * blockDim.x + threadIdx.x) >> 5;
    if (gw >= NN * NHEADS) return;
    int l = threadIdx.x & 31;
    int n = gw >> 2, h = gw & 3;
    float4 gv = ((const float4*)d_g)[(size_t)n * 128 + h * 32 + l];
    float4 sv = ((const float4*)att_s)[h * 32 + l];
    float4 dv = ((const float4*)att_d)[h * 32 + l];
    float as = gv.x * sv.x + gv.y * sv.y + gv.z * sv.z + gv.w * sv.w;
    float ad = gv.x * dv.x + gv.y * dv.y + gv.z * dv.z + gv.w * dv.w;
#pragma unroll
    for (int o = 16; o; o >>= 1) {
        as += __shfl_xor_sync(0xffffffffu, as, o);
        ad += __shfl_xor_sync(0xffffffffu, ad, o);
    }
    if (l == 0) { d_as[n * 4 + h] = as; d_ad[n * 4 + h] = ad; }
}

// GAT softmax-aggregate per dst node + fused mean-pool accumulate.
// No max subtraction (shift-invariant; logits far from fp32 overflow).
// exp() computed once per (edge, head) by 32 threads into smem.
__global__ void k_gat_agg(const int* __restrict__ batch,
                          const float* __restrict__ b_gat) {
    __shared__ float4 se[32];
    __shared__ int    ss[32];
    int n = blockIdx.x;
    int tid = threadIdx.x;
    int beg = d_rowptr[n], end = d_rowptr[n + 1];

    float ad0 = d_ad[n * NHEADS + 0], ad1 = d_ad[n * NHEADS + 1];
    float ad2 = d_ad[n * NHEADS + 2], ad3 = d_ad[n * NHEADS + 3];
    float acc0 = 0.f, acc1 = 0.f, acc2 = 0.f, acc3 = 0.f;
    float den0 = 0.f, den1 = 0.f, den2 = 0.f, den3 = 0.f;
    const float4* as4 = (const float4*)d_as;

    for (int chunk = beg; chunk < end; chunk += 32) {
        int m = min(32, end - chunk);
        if (tid < m) {
            int s = d_csrsrc[chunk + tid];
            ss[tid] = s;
            float4 av = as4[s];
            float v0 = av.x + ad0; v0 = v0 > 0.f ? v0 : NEG_SLOPE * v0;
            float v1 = av.y + ad1; v1 = v1 > 0.f ? v1 : NEG_SLOPE * v1;
            float v2 = av.z + ad2; v2 = v2 > 0.f ? v2 : NEG_SLOPE * v2;
            float v3 = av.w + ad3; v3 = v3 > 0.f ? v3 : NEG_SLOPE * v3;
            se[tid] = make_float4(__expf(v0), __expf(v1), __expf(v2), __expf(v3));
        }
        __syncthreads();
        for (int t = 0; t < m; t++) {
            int s = ss[t];
            float4 e = se[t];
            den0 += e.x; den1 += e.y; den2 += e.z; den3 += e.w;
            const float* gs = d_g + (size_t)s * GDIM;
            acc0 += e.x * gs[tid];
            acc1 += e.y * gs[DIM + tid];
            acc2 += e.z * gs[2 * DIM + tid];
            acc3 += e.w * gs[3 * DIM + tid];
        }
        __syncthreads();
    }
    float o = acc0 / (den0 + 1e-16f) + acc1 / (den1 + 1e-16f)
            + acc2 / (den2 + 1e-16f) + acc3 / (den3 + 1e-16f);
    o = o * 0.25f + b_gat[tid];
    float hv = o > 0.f ? o : __expf(o) - 1.f;
    d_h2[n * DIM + tid] = hv;
    int b = batch[n];
    atomicAdd(&d_pool[b * DIM + tid], hv);
    if (tid == 0) atomicAdd(&d_pcnt[b], 1.f);
}

// merged: blocks 0..4999 = wire/term heads (warp per node, 4 warps/block);
// blocks 5000..5015 = action logits (+ zero pool/pcnt after reading).
#define HEAD_BLOCKS 5000
__global__ void k_heads_logits(
        const float* __restrict__ Ww, const float* __restrict__ bw,
        const float* __restrict__ Wt, const float* __restrict__ bt,
        const float* __restrict__ Wa, const float* __restrict__ ba,
        float* __restrict__ out) {
    if (blockIdx.x < HEAD_BLOCKS) {
        int w = (blockIdx.x * blockDim.x + threadIdx.x) >> 5;
        if (w >= NN) return;
        int lane = threadIdx.x & 31;
        const float* Wv;
        float bias;
        if (w < NN - 10) { Wv = Ww; bias = bw[0]; }
        else             { Wv = Wt; bias = bt[0]; }
        float a = 0.f;
#pragma unroll
        for (int c = lane; c < DIM; c += 32) a += d_h2[w * DIM + c] * Wv[c];
#pragma unroll
        for (int off = 16; off > 0; off >>= 1)
            a += __shfl_xor_sync(0xffffffffu, a, off);
        if (lane == 0) out[w] = 1.f / (1.f + __expf(-(a + bias)));
    } else {
        __shared__ float sp[DIM];
        int b = blockIdx.x - HEAD_BLOCKS;
        int tid = threadIdx.x;
        float cnt = fmaxf(d_pcnt[b], 1.f);
        sp[tid] = d_pool[b * DIM + tid] / cnt;
        __syncthreads();
        if (tid < NACT) {
            float a = ba[tid];
#pragma unroll 8
            for (int c = 0; c < DIM; c++) a += sp[c] * Wa[c * NACT + tid];
            out[NN + b * NACT + tid] = a;
        }
        // leave pool/pcnt zeroed for the next graph replay
        d_pool[b * DIM + tid] = 0.f;
        if (tid == 0) d_pcnt[b] = 0.f;
    }
}

// ---------------- launch ----------------
extern "C" void kernel_launch(void* const* d_in, const int* in_sizes, int n_in,
                              void* d_out, int out_size) {
    const float* x     = (const float*)d_in[0];
    const int*   ei    = (const int*)d_in[1];
    const int*   batch = (const int*)d_in[2];
    const float* Wl   = (const float*)d_in[3];
    const float* Wr   = (const float*)d_in[4];
    const float* bs   = (const float*)d_in[5];
    const float* Wg   = (const float*)d_in[6];
    const float* ats  = (const float*)d_in[7];
    const float* atd  = (const float*)d_in[8];
    const float* bg   = (const float*)d_in[9];
    const float* Ww   = (const float*)d_in[10];
    const float* bw   = (const float*)d_in[11];
    const float* Wt   = (const float*)d_in[12];
    const float* bt   = (const float*)d_in[13];
    const float* Wa   = (const float*)d_in[14];
    const float* ba   = (const float*)d_in[15];
    float* out = (float*)d_out;

    k_count<<<EE / 256, 256>>>(ei);
    k_scan<<<1, 1024>>>();
    k_scatter<<<EE / 256, 256>>>(ei);
    k_sage_agg<<<NN, DIM>>>(x);
    k_sage_lin<<<NN / 8, DIM>>>(x, Wl, Wr, bs);
    k_gat_lin<<<NN / 16, GDIM>>>(Wg);
    k_attn<<<(NN * NHEADS * 32) / 256, 256>>>(ats, atd);
    k_gat_agg<<<NN, DIM>>>(batch, bg);
    k_heads_logits<<<HEAD_BLOCKS + NB, 128>>>(Ww, bw, Wt, bt, Wa, ba, out);
}